// round 3
// baseline (speedup 1.0000x reference)
#include <cuda_runtime.h>
#include <cuda_fp16.h>
#include <cstdint>
#include <math_constants.h>

// Fixed shapes for SparseMPNN_30709016166923
#define B_ 2
#define N_ 40000
#define E_ 640000
#define H_ 4
#define F_ 32
#define HF_ 128
#define NB_ (B_ * N_)          // 80000 segments (b, target-node)
#define NE_ (B_ * E_)          // 1280000 edges
#define NEG_SLOPE 0.2f

#define SCAN_BLK 1024
#define NBLK ((NB_ + SCAN_BLK - 1) / SCAN_BLK)   // 79

// Scratch (__device__ globals; no allocations allowed)
__device__ float   d_eself[NB_ * H_];
__device__ float   d_eadjc[NB_ * H_];
__device__ __half2 d_xh[NB_ * (HF_ / 2)];   // fp16 copy of X, 20.5 MB
__device__ int     d_cnt[NB_];
__device__ int     d_rowp[NB_];
__device__ int     d_cursor[NB_];
__device__ int     d_bsum[NBLK];
__device__ int     d_boff[NBLK];
__device__ int     d_srcl[NE_];             // CSR: source id per edge slot

__device__ __forceinline__ float lrelu(float x) {
    return x > 0.0f ? x : NEG_SLOPE * x;
}

// K1: per-node logits + fp16 conversion of X; one warp per (b,n); zero d_cnt.
__global__ void k1_node_logits(const float* __restrict__ X,
                               const float* __restrict__ As,
                               const float* __restrict__ Aa) {
    int warp = (blockIdx.x * blockDim.x + threadIdx.x) >> 5;
    int lane = threadIdx.x & 31;
    if (warp >= NB_) return;

    float4 x  = __ldg((const float4*)(X) + (size_t)warp * (HF_ / 4) + lane);
    int h = lane >> 3, j = lane & 7;
    float4 as = __ldg((const float4*)(As) + h * 8 + j);
    float4 aa = __ldg((const float4*)(Aa) + h * 8 + j);

    // fp16 copy (lane writes 8B: two half2)
    __half2 h0 = __floats2half2_rn(x.x, x.y);
    __half2 h1 = __floats2half2_rn(x.z, x.w);
    d_xh[(size_t)warp * (HF_ / 2) + lane * 2 + 0] = h0;
    d_xh[(size_t)warp * (HF_ / 2) + lane * 2 + 1] = h1;

    float ds = x.x * as.x + x.y * as.y + x.z * as.z + x.w * as.w;
    float da = x.x * aa.x + x.y * aa.y + x.z * aa.z + x.w * aa.w;
    #pragma unroll
    for (int m = 1; m < 8; m <<= 1) {
        ds += __shfl_xor_sync(0xFFFFFFFFu, ds, m);
        da += __shfl_xor_sync(0xFFFFFFFFu, da, m);
    }
    if (j == 0) {
        int o = warp * H_ + h;
        d_eself[o] = ds;
        d_eadjc[o] = da;
    }
    if (lane == 0) d_cnt[warp] = 0;
}

// Count edges per (b, target)
__global__ void ka_count(const int* __restrict__ tg) {
    int i = blockIdx.x * blockDim.x + threadIdx.x;
    if (i >= NE_) return;
    int b = i / E_;
    atomicAdd(&d_cnt[b * N_ + tg[i]], 1);
}

// Scan stage 1: per-block exclusive scan + block totals
__global__ void scan_a() {
    __shared__ int sm[SCAN_BLK];
    int t = threadIdx.x;
    int i = blockIdx.x * SCAN_BLK + t;
    int v = (i < NB_) ? d_cnt[i] : 0;
    sm[t] = v;
    __syncthreads();
    #pragma unroll
    for (int off = 1; off < SCAN_BLK; off <<= 1) {
        int u = (t >= off) ? sm[t - off] : 0;
        __syncthreads();
        sm[t] += u;
        __syncthreads();
    }
    if (i < NB_) d_rowp[i] = sm[t] - v;
    if (t == SCAN_BLK - 1) d_bsum[blockIdx.x] = sm[t];
}

// Scan stage 2: scan the 79 block sums
__global__ void scan_b() {
    __shared__ int sm[128];
    int t = threadIdx.x;
    int v = (t < NBLK) ? d_bsum[t] : 0;
    sm[t] = v;
    __syncthreads();
    #pragma unroll
    for (int off = 1; off < 128; off <<= 1) {
        int u = (t >= off) ? sm[t - off] : 0;
        __syncthreads();
        sm[t] += u;
        __syncthreads();
    }
    if (t < NBLK) d_boff[t] = sm[t] - v;
}

// Scan stage 3: add block offsets; init cursors
__global__ void scan_c() {
    int i = blockIdx.x * blockDim.x + threadIdx.x;
    if (i >= NB_) return;
    int r = d_rowp[i] + d_boff[i >> 10];
    d_rowp[i] = r;
    d_cursor[i] = r;
}

// Fill CSR source list
__global__ void kc_fill(const int* __restrict__ tg, const int* __restrict__ sc) {
    int i = blockIdx.x * blockDim.x + threadIdx.x;
    if (i >= NE_) return;
    int b = i / E_;
    int pos = atomicAdd(&d_cursor[b * N_ + tg[i]], 1);
    d_srcl[pos] = sc[i];
}

// K3: one warp per (b, target); gather fp16 X rows (256B/edge), fp32 math.
//   acc = sum_k exp(e_k) * X[src_k];  m = max e_k;  out = exp(-m) * acc
__global__ void k3_gather(float* __restrict__ out) {
    int w = (blockIdx.x * blockDim.x + threadIdx.x) >> 5;
    int lane = threadIdx.x & 31;
    if (w >= NB_) return;

    int len = d_cnt[w];
    float4* o = (float4*)out + (size_t)w * (HF_ / 4) + lane;
    if (len == 0) {
        *o = make_float4(0.f, 0.f, 0.f, 0.f);
        return;
    }
    int start = d_rowp[w];
    int b = w / N_;
    int h = lane >> 3;
    size_t bbase = (size_t)b * N_;

    float esh = d_eself[w * H_ + h];
    float mx = -CUDART_INF_F;
    float a0 = 0.f, a1 = 0.f, a2 = 0.f, a3 = 0.f;

    const int* sl = d_srcl + start;
    int s = __ldg(sl);
    for (int k = 0; k < len; k++) {
        int s_nxt = (k + 1 < len) ? __ldg(sl + k + 1) : 0;
        float eah = __ldg(d_eadjc + (bbase + s) * H_ + h);
        uint2 p = __ldg((const uint2*)(d_xh + (bbase + s) * (HF_ / 2)) + lane);
        float e = lrelu(esh + eah);
        float wt = __expf(e);
        mx = fmaxf(mx, e);
        float2 f0 = __half22float2(*reinterpret_cast<__half2*>(&p.x));
        float2 f1 = __half22float2(*reinterpret_cast<__half2*>(&p.y));
        a0 = fmaf(wt, f0.x, a0);
        a1 = fmaf(wt, f0.y, a1);
        a2 = fmaf(wt, f1.x, a2);
        a3 = fmaf(wt, f1.y, a3);
        s = s_nxt;
    }
    float scl = __expf(-mx);
    *o = make_float4(a0 * scl, a1 * scl, a2 * scl, a3 * scl);
}

extern "C" void kernel_launch(void* const* d_in, const int* in_sizes, int n_in,
                              void* d_out, int out_size) {
    const float* X  = (const float*)d_in[0];   // [B,N,H,F]
    const float* As = (const float*)d_in[1];   // [H,F]
    const float* Aa = (const float*)d_in[2];   // [H,F]
    // d_in[3] = degree (unused by reference)
    const int* tg = (const int*)d_in[4];       // [B,E]
    const int* sc = (const int*)d_in[5];       // [B,E]
    float* out = (float*)d_out;                // [B,N,H,F]
    (void)in_sizes; (void)n_in; (void)out_size;

    k1_node_logits<<<(NB_ * 32 + 255) / 256, 256>>>(X, As, Aa);
    ka_count<<<(NE_ + 255) / 256, 256>>>(tg);
    scan_a<<<NBLK, SCAN_BLK>>>();
    scan_b<<<1, 128>>>();
    scan_c<<<(NB_ + 255) / 256, 256>>>();
    kc_fill<<<(NE_ + 255) / 256, 256>>>(tg, sc);
    k3_gather<<<(NB_ * 32 + 255) / 256, 256>>>(out);
}